// round 13
// baseline (speedup 1.0000x reference)
#include <cuda_runtime.h>
#include <math.h>

#define B_   16
#define H_   128
#define W_   64
#define T_   64
#define NLOC (B_ * H_ * W_)

// Scratch: spike bitmasks (1 bit per timestep)
__device__ unsigned long long g_xbits[NLOC];
__device__ unsigned long long g_s1bits[NLOC];

// ---------------------------------------------------------------------------
// Kernel 0: pack input floats (exactly 0.0 / 1.0) into per-neuron bitmasks.
// Thread-per-location, 16 independent float4 loads (high MLP).
// ---------------------------------------------------------------------------
__global__ void __launch_bounds__(256) pack_kernel(const float* __restrict__ in) {
    const int loc = blockIdx.x * 256 + threadIdx.x;
    const float4* p = (const float4*)(in + (size_t)loc * T_);
    unsigned long long m = 0ull;
#pragma unroll
    for (int i = 0; i < 16; ++i) {
        float4 v = p[i];
        unsigned long long b = 0ull;
        if (v.x != 0.0f) b |= 1ull;
        if (v.y != 0.0f) b |= 2ull;
        if (v.z != 0.0f) b |= 4ull;
        if (v.w != 0.0f) b |= 8ull;
        m |= b << (4 * i);
    }
    g_xbits[loc] = m;
}

// ---------------------------------------------------------------------------
// Fused layer kernel. Block = 4 output rows x 64 cols = 2x32 Winograd tiles,
// 128 threads: 2 threads per tile (tid&63 = tile, tid>>6 = ph -> 2 outputs).
// psp: EXACT sequential descending-j sum (memoized prefix LUT, verified R12).
// Refractory: 2nd-order IIR approximation (3 FMA) + epsilon-banded EXACT
// fallback over the exact spike window -> decision provably identical to the
// reference scan. Winograd F(2x2,3x3) op sequence identical to R6/R7/R9.
// ---------------------------------------------------------------------------
template <int LAYER>
__global__ void __launch_bounds__(128) fused_kernel(const float* __restrict__ wconv,
                                                    float* __restrict__ out) {
    constexpr int   FIRN  = (LAYER == 0) ? 8 : 16;
    constexpr int   JMAX  = (LAYER == 0) ? 17 : 35;
    constexpr float THETA = (LAYER == 0) ? 30.0f : 50.0f;
    constexpr float EPS   = 0.015625f;       // 2^-6; |r~ - r| <= ~1.5e-3
    constexpr int   HR    = 6;               // halo rows (4 + 2)
    constexpr int   HC    = 66;              // halo cols (64 + 2)
    constexpr int   NH    = HR * HC;         // 396
    constexpr int   TC    = 8;               // timestep chunk
    constexpr int   NPL   = (LAYER == 0) ? 128 : 256;   // psp prefix LUT size

    __shared__ __align__(16) float s_buf[TC][HR][72];   // psp tile, padded
    __shared__ float s_plut[4][NPL];                     // psp prefix LUT x4
    __shared__ float s_kk[FIRN];
    __shared__ float s_rk[JMAX + 1];
    __shared__ float s_w[9];

    const int tid = threadIdx.x;
    const int h0  = blockIdx.x * 4;
    const int b   = blockIdx.y;

    // --- taps in double, matching numpy exactly ---
    {
        const double tau   = (LAYER == 0) ? 1.0 : 2.0;
        const double rmult = (LAYER == 0) ? -60.0 : -100.0;  // -2*theta*scale_ref
        if (tid < FIRN) {
            double td = (double)tid;
            s_kk[tid] = (float)(((1.0 * td) / tau) * exp(1.0 - td / tau));
        }
        if (tid <= JMAX) {
            double td = (double)tid;
            double v  = ((rmult * td) / tau) * exp(1.0 - td / tau);
            s_rk[tid] = (tid == 0) ? 0.0f : (float)v;
        }
        if (tid < 9) s_w[tid] = wconv[tid];
    }
    __syncthreads();

    // IIR constants for the refractory recurrence (approximation only)
    const double a_d = exp((LAYER == 0) ? -1.0 : -0.5);
    const float  A1  = (float)(2.0 * a_d);
    const float  A2  = (float)(-a_d * a_d);
    const float  RK1 = s_rk[1];

    // --- psp prefix LUT: exact partial sum of the sequential descending-j
    //     FIR. Index bit m == lag j = (top) - m.
    //     L0: taps j=7..1 (7 bits, full sum).  L1: taps j=15..8 (prefix). ---
    for (int e = tid; e < NPL; e += 128) {
        float v = 0.0f;
        if (LAYER == 0) {
#pragma unroll
            for (int j = 7; j >= 1; --j)
                if ((e >> (7 - j)) & 1) v = __fadd_rn(v, s_kk[j]);
        } else {
#pragma unroll
            for (int j = 15; j >= 8; --j)
                if ((e >> (15 - j)) & 1) v = __fadd_rn(v, s_kk[j]);
        }
#pragma unroll
        for (int cp = 0; cp < 4; ++cp) s_plut[cp][e] = v;
    }
    __syncthreads();

    float kk[8];                     // L1 continuation taps j=1..7
#pragma unroll
    for (int k = 0; k < 8; ++k) kk[k] = s_kk[k];

    // --- weight transform U = G g G^T, exact-half form (identical to R6) ---
    float U[4][4];
    {
        float q[4][3];
#pragma unroll
        for (int j = 0; j < 3; ++j) {
            float g0 = s_w[j], g1 = s_w[3 + j], g2 = s_w[6 + j];
            float s  = __fadd_rn(g0, g2);
            q[0][j] = g0;
            q[1][j] = __fmul_rn(0.5f, __fadd_rn(s, g1));
            q[2][j] = __fmul_rn(0.5f, __fsub_rn(s, g1));
            q[3][j] = g2;
        }
#pragma unroll
        for (int i = 0; i < 4; ++i) {
            float q0 = q[i][0], q1 = q[i][1], q2 = q[i][2];
            float s  = __fadd_rn(q0, q2);
            U[i][0] = q0;
            U[i][1] = __fmul_rn(0.5f, __fadd_rn(s, q1));
            U[i][2] = __fmul_rn(0.5f, __fsub_rn(s, q1));
            U[i][3] = q2;
        }
    }

    // --- halo bitmask load: rows h0-1..h0+4, cols -1..64, zeros outside ---
    const unsigned long long* bits = (LAYER == 0) ? g_xbits : g_s1bits;
    unsigned long long hm[4];
    int soff[4];
#pragma unroll
    for (int k = 0; k < 4; ++k) {
        int l  = tid + 128 * k;
        int hr = l / HC, hc = l % HC;
        bool valid = (l < NH);
        int grow = h0 - 1 + hr, gcol = hc - 1;
        unsigned long long v = 0ull;
        if (valid && (unsigned)grow < (unsigned)H_ && (unsigned)gcol < (unsigned)W_)
            v = bits[(b * H_ + grow) * W_ + gcol];
        hm[k]   = v;
        soff[k] = valid ? hr * 72 + hc : 5 * 72 + 66;   // pad slot if invalid
    }

    const float* pl = &s_plut[(tid & 31) >> 3][0];

    const int tile = tid & 63;
    const int ph   = tid >> 6;           // 0 or 1: output row within tile
    const int tr   = tile >> 5;          // tile row 0..1
    const int tcix = tile & 31;          // tile col 0..31
    const int row0 = 2 * tr;
    const int col0 = 2 * tcix;

    unsigned long long sm[2]  = {0ull, 0ull};
    unsigned long long win[2] = {0ull, 0ull};
    float r1[2] = {0.0f, 0.0f};          // r~(t-1)
    float r2[2] = {0.0f, 0.0f};          // r~(t-2)
    float sf[2] = {0.0f, 0.0f};          // spike(t-1) as float

    for (int tb = 0; tb < T_; tb += TC) {
        // ---- psp fill: exact sequential descending-j via prefix LUT ----
#pragma unroll
        for (int k = 0; k < 4; ++k) {
            unsigned long long mk = hm[k];
            float* dst = &s_buf[0][0][0] + soff[k];
#pragma unroll 4
            for (int dt = 0; dt < TC; ++dt) {
                int t = tb + dt;
                unsigned long long mt = mk << (63 - t);  // bit 63-j == spike t-j
                float acc;
                if (LAYER == 0) {
                    acc = pl[(unsigned)(mt >> 56) & 0x7Fu];      // j=7..1 exact
                } else {
                    acc = pl[(unsigned)(mt >> 48) & 0xFFu];      // j=15..8 prefix
#pragma unroll
                    for (int j = 7; j >= 1; --j)                 // continue j=7..1
                        if ((mt >> (63 - j)) & 1ull) acc = __fadd_rn(acc, kk[j]);
                }
                dst[dt * (HR * 72)] = acc;
            }
        }
        __syncthreads();

        // ---- consume: Winograd + spike scan, 2 outputs per thread ----
#pragma unroll 4
        for (int dt = 0; dt < TC; ++dt) {
            int t = tb + dt;

            float rx[4][4];
#pragma unroll
            for (int r = 0; r < 4; ++r) {
                float2 a = *(const float2*)&s_buf[dt][row0 + r][col0];
                float2 c = *(const float2*)&s_buf[dt][row0 + r][col0 + 2];
                rx[r][0] = a.x; rx[r][1] = a.y; rx[r][2] = c.x; rx[r][3] = c.y;
            }

            float tt[4][4];
#pragma unroll
            for (int c = 0; c < 4; ++c) {
                tt[0][c] = __fsub_rn(rx[0][c], rx[2][c]);
                tt[1][c] = __fadd_rn(rx[1][c], rx[2][c]);
                tt[2][c] = __fsub_rn(rx[2][c], rx[1][c]);
                tt[3][c] = __fsub_rn(rx[1][c], rx[3][c]);
            }

            float s[4];
#pragma unroll
            for (int j = 0; j < 4; ++j) {
                float M[4];
#pragma unroll
                for (int i = 0; i < 4; ++i) {
                    float t0 = tt[i][0], t1 = tt[i][1], t2 = tt[i][2], t3 = tt[i][3];
                    float Vij = (j == 0) ? __fsub_rn(t0, t2)
                              : (j == 1) ? __fadd_rn(t1, t2)
                              : (j == 2) ? __fsub_rn(t2, t1)
                                         : __fsub_rn(t1, t3);
                    M[i] = __fmul_rn(U[i][j], Vij);
                }
                s[j] = (ph == 0) ? __fadd_rn(__fadd_rn(M[0], M[1]), M[2])
                                 : __fsub_rn(__fsub_rn(M[1], M[2]), M[3]);
            }
            float y[2];
            y[0] = __fadd_rn(__fadd_rn(s[0], s[1]), s[2]);   // pw = 0
            y[1] = __fsub_rn(__fsub_rn(s[1], s[2]), s[3]);   // pw = 1

#pragma unroll
            for (int p = 0; p < 2; ++p) {
                // IIR refractory approximation: 3 FMA, no memory
                float rt = fmaf(A1, r1[p], fmaf(A2, r2[p], __fmul_rn(RK1, sf[p])));
                float d  = __fsub_rn(__fadd_rn(y[p], rt), THETA);
                bool spike;
                if (fabsf(d) <= EPS) {
                    // EXACT fallback: descending-j predicated adds (== reference)
                    float rxv = 0.0f;
#pragma unroll 1
                    for (int j = JMAX; j >= 1; --j)
                        if ((win[p] >> (j - 1)) & 1ull) rxv = __fadd_rn(rxv, s_rk[j]);
                    spike = (__fadd_rn(y[p], rxv) >= THETA);
                } else {
                    spike = (d > 0.0f);
                }
                unsigned long long sp = spike ? 1ull : 0ull;
                sm[p]  |= sp << t;
                win[p]  = (win[p] << 1) | sp;
                r2[p] = r1[p];
                r1[p] = rt;
                sf[p] = spike ? 1.0f : 0.0f;
            }
        }
        __syncthreads();
    }

    // ---- epilogue ----
#pragma unroll
    for (int p = 0; p < 2; ++p) {
        const int h   = h0 + 2 * tr + ph;
        const int wc  = 2 * tcix + p;
        const int loc = (b * H_ + h) * W_ + wc;
        if (LAYER == 0) {
            g_s1bits[loc] = sm[p];
        } else {
            float4* o = (float4*)(out + (size_t)loc * T_);
            const unsigned long long sv = sm[p];
#pragma unroll
            for (int i = 0; i < 16; ++i) {
                float4 v;
                v.x = ((sv >> (4 * i + 0)) & 1ull) ? 1.0f : 0.0f;
                v.y = ((sv >> (4 * i + 1)) & 1ull) ? 1.0f : 0.0f;
                v.z = ((sv >> (4 * i + 2)) & 1ull) ? 1.0f : 0.0f;
                v.w = ((sv >> (4 * i + 3)) & 1ull) ? 1.0f : 0.0f;
                o[i] = v;
            }
        }
    }
}

// ---------------------------------------------------------------------------
extern "C" void kernel_launch(void* const* d_in, const int* in_sizes, int n_in,
                              void* d_out, int out_size) {
    const float* x  = (const float*)d_in[0];
    const float* w1 = (const float*)d_in[1];
    const float* w2 = (const float*)d_in[2];
    float* out = (float*)d_out;

    pack_kernel<<<NLOC / 256, 256>>>(x);

    dim3 fblk(128), fgrd(H_ / 4, B_);
    fused_kernel<0><<<fgrd, fblk>>>(w1, nullptr);
    fused_kernel<1><<<fgrd, fblk>>>(w2, out);
}

// round 14
// speedup vs baseline: 1.1045x; 1.1045x over previous
#include <cuda_runtime.h>
#include <math.h>

#define B_   16
#define H_   128
#define W_   64
#define T_   64
#define NLOC (B_ * H_ * W_)

// Scratch: spike bitmasks (1 bit per timestep)
__device__ unsigned long long g_xbits[NLOC];
__device__ unsigned long long g_s1bits[NLOC];

// ---------------------------------------------------------------------------
// Kernel 0: pack input floats (exactly 0.0 / 1.0) into per-neuron bitmasks.
// Ballot version (fully coalesced loads).
// ---------------------------------------------------------------------------
__global__ void __launch_bounds__(256) pack_kernel(const float* __restrict__ in) {
    const int lane = threadIdx.x & 31;
    const int w0   = threadIdx.x & 32;
    const int h    = blockIdx.x * 4 + threadIdx.y;
    const int b    = blockIdx.y;
    const int loc0 = (b * H_ + h) * W_ + w0;
    const size_t gbase = (size_t)loc0 * T_;

    unsigned lo = 0u, hi = 0u;
#pragma unroll
    for (int i = 0; i < 64; ++i) {
        float v = in[gbase + i * 32 + lane];
        unsigned bal = __ballot_sync(0xffffffffu, v != 0.0f);
        if (lane == (i >> 1)) {
            if (i & 1) hi = bal; else lo = bal;
        }
    }
    g_xbits[loc0 + lane] = ((unsigned long long)hi << 32) | (unsigned long long)lo;
}

// ---------------------------------------------------------------------------
// Fused layer kernel (R9 geometry): 128 threads = 4x32 Winograd tiles ->
// 8 rows x 64 cols outputs, 4 outputs/thread, 4 independent refractory chains.
// psp: EXACT sequential descending-j sum via memoized prefix LUT
//   L0: full 7-tap LUT (index bit k == lag j=7-k).
//   L1: prefix LUT over j=15..8 (index bit m == lag j=15-m) + taps j=7..1.
// Refractory: exact descending-j predicated adds over 32-bit window halves
// (same adds, same order as the reference buffer scan -> bit-identical).
// Winograd F(2x2,3x3) op sequence identical to R6/R7/R9.
// ---------------------------------------------------------------------------
template <int LAYER>
__global__ void __launch_bounds__(128) fused_kernel(const float* __restrict__ wconv,
                                                    float* __restrict__ out) {
    constexpr int   FIRN  = (LAYER == 0) ? 8 : 16;
    constexpr int   JMAX  = (LAYER == 0) ? 17 : 35;
    constexpr float THETA = (LAYER == 0) ? 30.0f : 50.0f;
    constexpr int   HR    = 10;              // halo rows (8 + 2)
    constexpr int   HC    = 66;              // halo cols (64 + 2)
    constexpr int   NH    = HR * HC;         // 660
    constexpr int   TC    = 8;               // timestep chunk
    constexpr int   NPL   = (LAYER == 0) ? 128 : 256;   // psp prefix LUT size

    __shared__ __align__(16) float s_buf[TC][HR][72];   // psp tile, padded
    __shared__ float s_plut[4][NPL];                     // psp prefix LUT x4
    __shared__ float s_kk[FIRN];
    __shared__ float s_rk[JMAX + 1];
    __shared__ float s_w[9];

    const int tid = threadIdx.x;
    const int h0  = blockIdx.x * 8;
    const int b   = blockIdx.y;

    // --- taps in double, matching numpy exactly ---
    {
        const double tau   = (LAYER == 0) ? 1.0 : 2.0;
        const double rmult = (LAYER == 0) ? -60.0 : -100.0;  // -2*theta*scale_ref
        if (tid < FIRN) {
            double td = (double)tid;
            s_kk[tid] = (float)(((1.0 * td) / tau) * exp(1.0 - td / tau));
        }
        if (tid <= JMAX) {
            double td = (double)tid;
            double v  = ((rmult * td) / tau) * exp(1.0 - td / tau);
            s_rk[tid] = (tid == 0) ? 0.0f : (float)v;
        }
        if (tid < 9) s_w[tid] = wconv[tid];
    }
    __syncthreads();

    // --- psp prefix LUT (exact partial sums of the descending-j sequence) ---
    for (int e = tid; e < NPL; e += 128) {
        float v = 0.0f;
        if (LAYER == 0) {
#pragma unroll
            for (int j = 7; j >= 1; --j)
                if ((e >> (7 - j)) & 1) v = __fadd_rn(v, s_kk[j]);
        } else {
#pragma unroll
            for (int j = 15; j >= 8; --j)
                if ((e >> (15 - j)) & 1) v = __fadd_rn(v, s_kk[j]);
        }
#pragma unroll
        for (int cp = 0; cp < 4; ++cp) s_plut[cp][e] = v;
    }
    __syncthreads();

    float kk[8];                     // L1 continuation taps j=1..7
#pragma unroll
    for (int k = 0; k < 8; ++k) kk[k] = s_kk[k];
    float rk[JMAX + 1];
#pragma unroll
    for (int j = 0; j <= JMAX; ++j) rk[j] = s_rk[j];

    // --- weight transform U = G g G^T, exact-half form (identical to R6) ---
    float U[4][4];
    {
        float q[4][3];
#pragma unroll
        for (int j = 0; j < 3; ++j) {
            float g0 = s_w[j], g1 = s_w[3 + j], g2 = s_w[6 + j];
            float s  = __fadd_rn(g0, g2);
            q[0][j] = g0;
            q[1][j] = __fmul_rn(0.5f, __fadd_rn(s, g1));
            q[2][j] = __fmul_rn(0.5f, __fsub_rn(s, g1));
            q[3][j] = g2;
        }
#pragma unroll
        for (int i = 0; i < 4; ++i) {
            float q0 = q[i][0], q1 = q[i][1], q2 = q[i][2];
            float s  = __fadd_rn(q0, q2);
            U[i][0] = q0;
            U[i][1] = __fmul_rn(0.5f, __fadd_rn(s, q1));
            U[i][2] = __fmul_rn(0.5f, __fsub_rn(s, q1));
            U[i][3] = q2;
        }
    }

    // --- halo bitmask load: rows h0-1..h0+8, cols -1..64, zeros outside ---
    const unsigned long long* bits = (LAYER == 0) ? g_xbits : g_s1bits;
    unsigned long long hm[6];
    int soff[6];
#pragma unroll
    for (int k = 0; k < 6; ++k) {
        int l  = tid + 128 * k;
        int hr = l / HC, hc = l % HC;
        bool valid = (l < NH);
        int grow = h0 - 1 + hr, gcol = hc - 1;
        unsigned long long v = 0ull;
        if (valid && (unsigned)grow < (unsigned)H_ && (unsigned)gcol < (unsigned)W_)
            v = bits[(b * H_ + grow) * W_ + gcol];
        hm[k]   = v;
        soff[k] = valid ? hr * 72 + hc : 9 * 72 + 66;   // pad slot if invalid
    }

    const float* pl = &s_plut[(tid & 31) >> 3][0];

    const int tr   = tid >> 5;           // tile row 0..3
    const int tcix = tid & 31;           // tile col 0..31
    const int row0 = 2 * tr;
    const int col0 = 2 * tcix;

    unsigned long long sm[4]  = {0ull, 0ull, 0ull, 0ull};
    unsigned long long win[4] = {0ull, 0ull, 0ull, 0ull};

    for (int tb = 0; tb < T_; tb += TC) {
        // ---- psp fill: exact sequential descending-j via prefix LUT ----
#pragma unroll
        for (int k = 0; k < 6; ++k) {
            unsigned long long mk = hm[k];
            float* dst = &s_buf[0][0][0] + soff[k];
#pragma unroll 4
            for (int dt = 0; dt < TC; ++dt) {
                int t = tb + dt;
                unsigned long long mt = mk << (63 - t);  // bit 63-j == spike t-j
                float acc;
                if (LAYER == 0) {
                    acc = pl[(unsigned)(mt >> 56) & 0x7Fu];      // j=7..1 exact
                } else {
                    acc = pl[(unsigned)(mt >> 48) & 0xFFu];      // j=15..8 prefix
#pragma unroll
                    for (int j = 7; j >= 1; --j)                 // continue j=7..1
                        if ((mt >> (63 - j)) & 1ull) acc = __fadd_rn(acc, kk[j]);
                }
                dst[dt * (HR * 72)] = acc;
            }
        }
        __syncthreads();

        // ---- consume: Winograd + spike scan, 4 outputs per thread ----
#pragma unroll 4
        for (int dt = 0; dt < TC; ++dt) {
            int t = tb + dt;

            float rx[4][4];
#pragma unroll
            for (int r = 0; r < 4; ++r) {
                float2 a = *(const float2*)&s_buf[dt][row0 + r][col0];
                float2 c = *(const float2*)&s_buf[dt][row0 + r][col0 + 2];
                rx[r][0] = a.x; rx[r][1] = a.y; rx[r][2] = c.x; rx[r][3] = c.y;
            }

            float tt[4][4];
#pragma unroll
            for (int c = 0; c < 4; ++c) {
                tt[0][c] = __fsub_rn(rx[0][c], rx[2][c]);
                tt[1][c] = __fadd_rn(rx[1][c], rx[2][c]);
                tt[2][c] = __fsub_rn(rx[2][c], rx[1][c]);
                tt[3][c] = __fsub_rn(rx[1][c], rx[3][c]);
            }

            float s0[4], s1[4];
#pragma unroll
            for (int j = 0; j < 4; ++j) {
                float M[4];
#pragma unroll
                for (int i = 0; i < 4; ++i) {
                    float t0 = tt[i][0], t1 = tt[i][1], t2 = tt[i][2], t3 = tt[i][3];
                    float Vij = (j == 0) ? __fsub_rn(t0, t2)
                              : (j == 1) ? __fadd_rn(t1, t2)
                              : (j == 2) ? __fsub_rn(t2, t1)
                                         : __fsub_rn(t1, t3);
                    M[i] = __fmul_rn(U[i][j], Vij);
                }
                s0[j] = __fadd_rn(__fadd_rn(M[0], M[1]), M[2]);
                s1[j] = __fsub_rn(__fsub_rn(M[1], M[2]), M[3]);
            }
            float y[4];
            y[0] = __fadd_rn(__fadd_rn(s0[0], s0[1]), s0[2]);   // (0,0)
            y[1] = __fsub_rn(__fsub_rn(s0[1], s0[2]), s0[3]);   // (0,1)
            y[2] = __fadd_rn(__fadd_rn(s1[0], s1[1]), s1[2]);   // (1,0)
            y[3] = __fsub_rn(__fsub_rn(s1[1], s1[2]), s1[3]);   // (1,1)

#pragma unroll
            for (int p = 0; p < 4; ++p) {
                // exact refractory: descending-j predicated adds, 32-bit halves
                const unsigned wlo = (unsigned)win[p];
                const unsigned whi = (unsigned)(win[p] >> 32);
                float r = 0.0f;
                if (JMAX > 32) {
#pragma unroll
                    for (int j = JMAX; j >= 33; --j)
                        if ((whi >> (j - 33)) & 1u) r = __fadd_rn(r, rk[j]);
                }
#pragma unroll
                for (int j = (JMAX > 32 ? 32 : JMAX); j >= 1; --j)
                    if ((wlo >> (j - 1)) & 1u) r = __fadd_rn(r, rk[j]);

                float m = __fadd_rn(y[p], r);
                unsigned long long sp = (m >= THETA) ? 1ull : 0ull;
                sm[p]  |= sp << t;
                win[p]  = (win[p] << 1) | sp;
            }
        }
        __syncthreads();
    }

    // ---- epilogue ----
#pragma unroll
    for (int p = 0; p < 4; ++p) {
        const int h   = h0 + 2 * tr + (p >> 1);
        const int wc  = 2 * tcix + (p & 1);
        const int loc = (b * H_ + h) * W_ + wc;
        if (LAYER == 0) {
            g_s1bits[loc] = sm[p];
        } else {
            float4* o = (float4*)(out + (size_t)loc * T_);
            const unsigned long long sv = sm[p];
#pragma unroll
            for (int i = 0; i < 16; ++i) {
                float4 v;
                v.x = ((sv >> (4 * i + 0)) & 1ull) ? 1.0f : 0.0f;
                v.y = ((sv >> (4 * i + 1)) & 1ull) ? 1.0f : 0.0f;
                v.z = ((sv >> (4 * i + 2)) & 1ull) ? 1.0f : 0.0f;
                v.w = ((sv >> (4 * i + 3)) & 1ull) ? 1.0f : 0.0f;
                o[i] = v;
            }
        }
    }
}

// ---------------------------------------------------------------------------
extern "C" void kernel_launch(void* const* d_in, const int* in_sizes, int n_in,
                              void* d_out, int out_size) {
    const float* x  = (const float*)d_in[0];
    const float* w1 = (const float*)d_in[1];
    const float* w2 = (const float*)d_in[2];
    float* out = (float*)d_out;

    dim3 pblk(64, 4), pgrd(H_ / 4, B_);
    pack_kernel<<<pgrd, pblk>>>(x);

    dim3 fblk(128), fgrd(H_ / 8, B_);
    fused_kernel<0><<<fgrd, fblk>>>(w1, nullptr);
    fused_kernel<1><<<fgrd, fblk>>>(w2, out);
}

// round 15
// speedup vs baseline: 1.3425x; 1.2155x over previous
#include <cuda_runtime.h>
#include <math.h>

#define B_   16
#define H_   128
#define W_   64
#define T_   64
#define NLOC (B_ * H_ * W_)

// Scratch: spike bitmasks (1 bit per timestep)
__device__ unsigned long long g_xbits[NLOC];
__device__ unsigned long long g_s1bits[NLOC];

// ---------------------------------------------------------------------------
// Kernel 0: pack input floats (exactly 0.0 / 1.0) into per-neuron bitmasks.
// ---------------------------------------------------------------------------
__global__ void __launch_bounds__(256) pack_kernel(const float* __restrict__ in) {
    const int lane = threadIdx.x & 31;
    const int w0   = threadIdx.x & 32;
    const int h    = blockIdx.x * 4 + threadIdx.y;
    const int b    = blockIdx.y;
    const int loc0 = (b * H_ + h) * W_ + w0;
    const size_t gbase = (size_t)loc0 * T_;

    unsigned lo = 0u, hi = 0u;
#pragma unroll
    for (int i = 0; i < 64; ++i) {
        float v = in[gbase + i * 32 + lane];
        unsigned bal = __ballot_sync(0xffffffffu, v != 0.0f);
        if (lane == (i >> 1)) {
            if (i & 1) hi = bal; else lo = bal;
        }
    }
    g_xbits[loc0 + lane] = ((unsigned long long)hi << 32) | (unsigned long long)lo;
}

// ---------------------------------------------------------------------------
// Fused layer kernel — R9 structure exactly, with ONE change: refractory is
// an IIR(2) approximation (3 FMA/output) + warp-voted EXACT fallback.
// If any lane's |y + r~ - theta| <= EPS, the whole warp uniformly recomputes
// the exact descending-j sum (reference scan order, s_rk broadcast LDS) ->
// decision provably identical to the reference everywhere.
// Winograd F(2x2,3x3) + psp fill identical to R9 (bit-exact, verified).
// ---------------------------------------------------------------------------
template <int LAYER>
__global__ void __launch_bounds__(128) fused_kernel(const float* __restrict__ wconv,
                                                    float* __restrict__ out) {
    constexpr int   FIRN  = (LAYER == 0) ? 8 : 16;
    constexpr int   JMAX  = (LAYER == 0) ? 17 : 35;
    constexpr float THETA = (LAYER == 0) ? 30.0f : 50.0f;
    constexpr float EPS   = 0.015625f;       // 2^-6, validated in R13
    constexpr int   HR    = 10;              // halo rows (8 + 2)
    constexpr int   HC    = 66;              // halo cols (64 + 2)
    constexpr int   NH    = HR * HC;         // 660
    constexpr int   TC    = 8;               // timestep chunk

    __shared__ __align__(16) float s_buf[TC][HR][72];   // psp tile, padded
    __shared__ float s_kk[FIRN];
    __shared__ float s_rk[JMAX + 1];
    __shared__ float s_w[9];

    const int tid = threadIdx.x;
    const int h0  = blockIdx.x * 8;
    const int b   = blockIdx.y;

    // --- taps in double, matching numpy exactly ---
    {
        const double tau   = (LAYER == 0) ? 1.0 : 2.0;
        const double rmult = (LAYER == 0) ? -60.0 : -100.0;  // -2*theta*scale_ref
        if (tid < FIRN) {
            double td = (double)tid;
            s_kk[tid] = (float)(((1.0 * td) / tau) * exp(1.0 - td / tau));
        }
        if (tid <= JMAX) {
            double td = (double)tid;
            double v  = ((rmult * td) / tau) * exp(1.0 - td / tau);
            s_rk[tid] = (tid == 0) ? 0.0f : (float)v;
        }
        if (tid < 9) s_w[tid] = wconv[tid];
    }
    __syncthreads();

    // IIR constants for the refractory recurrence (approximation only;
    // decisions are guarded by the epsilon band + exact fallback)
    const double a_d = exp((LAYER == 0) ? -1.0 : -0.5);
    const float  A1  = (float)(2.0 * a_d);
    const float  A2  = (float)(-a_d * a_d);
    const float  RK1 = s_rk[1];

    float kk[FIRN];
#pragma unroll
    for (int k = 0; k < FIRN; ++k) kk[k] = s_kk[k];

    // --- weight transform U = G g G^T, exact-half form (identical to R6) ---
    float U[4][4];
    {
        float q[4][3];
#pragma unroll
        for (int j = 0; j < 3; ++j) {
            float g0 = s_w[j], g1 = s_w[3 + j], g2 = s_w[6 + j];
            float s  = __fadd_rn(g0, g2);
            q[0][j] = g0;
            q[1][j] = __fmul_rn(0.5f, __fadd_rn(s, g1));
            q[2][j] = __fmul_rn(0.5f, __fsub_rn(s, g1));
            q[3][j] = g2;
        }
#pragma unroll
        for (int i = 0; i < 4; ++i) {
            float q0 = q[i][0], q1 = q[i][1], q2 = q[i][2];
            float s  = __fadd_rn(q0, q2);
            U[i][0] = q0;
            U[i][1] = __fmul_rn(0.5f, __fadd_rn(s, q1));
            U[i][2] = __fmul_rn(0.5f, __fsub_rn(s, q1));
            U[i][3] = q2;
        }
    }

    // --- halo bitmask load: rows h0-1..h0+8, cols -1..64, zeros outside ---
    const unsigned long long* bits = (LAYER == 0) ? g_xbits : g_s1bits;
    unsigned long long hm[6];
    int soff[6];
#pragma unroll
    for (int k = 0; k < 6; ++k) {
        int l  = tid + 128 * k;
        int hr = l / HC, hc = l % HC;
        bool valid = (l < NH);
        int grow = h0 - 1 + hr, gcol = hc - 1;
        unsigned long long v = 0ull;
        if (valid && (unsigned)grow < (unsigned)H_ && (unsigned)gcol < (unsigned)W_)
            v = bits[(b * H_ + grow) * W_ + gcol];
        hm[k]   = v;
        soff[k] = valid ? hr * 72 + hc : 9 * 72 + 66;   // pad slot if invalid
    }

    const int tr   = tid >> 5;           // tile row 0..3
    const int tcix = tid & 31;           // tile col 0..31
    const int row0 = 2 * tr;
    const int col0 = 2 * tcix;

    unsigned long long sm[4]  = {0ull, 0ull, 0ull, 0ull};
    unsigned long long win[4] = {0ull, 0ull, 0ull, 0ull};
    float r1[4] = {0.0f, 0.0f, 0.0f, 0.0f};   // r~(t-1)
    float r2[4] = {0.0f, 0.0f, 0.0f, 0.0f};   // r~(t-2)
    float sf[4] = {0.0f, 0.0f, 0.0f, 0.0f};   // spike(t-1) as float

    for (int tb = 0; tb < T_; tb += TC) {
        // ---- psp fill (descending lag j; j=0 tap is exactly 0 -> skipped) ----
#pragma unroll
        for (int k = 0; k < 6; ++k) {
            unsigned long long mk = hm[k];
            float* dst = &s_buf[0][0][0] + soff[k];
#pragma unroll 4
            for (int dt = 0; dt < TC; ++dt) {
                int t = tb + dt;
                unsigned long long mt = mk << (63 - t);  // bit 63-j == spike t-j
                float acc = 0.0f;
#pragma unroll
                for (int ki = 0; ki < FIRN - 1; ++ki) {
                    int j = FIRN - 1 - ki;               // descending lag
                    if ((mt >> (63 - j)) & 1ull) acc = __fadd_rn(acc, kk[j]);
                }
                dst[dt * (HR * 72)] = acc;
            }
        }
        __syncthreads();

        // ---- consume: Winograd + spike scan, 4 outputs per thread ----
#pragma unroll 2
        for (int dt = 0; dt < TC; ++dt) {
            int t = tb + dt;

            float rx[4][4];
#pragma unroll
            for (int r = 0; r < 4; ++r) {
                float2 a = *(const float2*)&s_buf[dt][row0 + r][col0];
                float2 c = *(const float2*)&s_buf[dt][row0 + r][col0 + 2];
                rx[r][0] = a.x; rx[r][1] = a.y; rx[r][2] = c.x; rx[r][3] = c.y;
            }

            float tt[4][4];
#pragma unroll
            for (int c = 0; c < 4; ++c) {
                tt[0][c] = __fsub_rn(rx[0][c], rx[2][c]);
                tt[1][c] = __fadd_rn(rx[1][c], rx[2][c]);
                tt[2][c] = __fsub_rn(rx[2][c], rx[1][c]);
                tt[3][c] = __fsub_rn(rx[1][c], rx[3][c]);
            }

            float s0[4], s1[4];
#pragma unroll
            for (int j = 0; j < 4; ++j) {
                float M[4];
#pragma unroll
                for (int i = 0; i < 4; ++i) {
                    float t0 = tt[i][0], t1 = tt[i][1], t2 = tt[i][2], t3 = tt[i][3];
                    float Vij = (j == 0) ? __fsub_rn(t0, t2)
                              : (j == 1) ? __fadd_rn(t1, t2)
                              : (j == 2) ? __fsub_rn(t2, t1)
                                         : __fsub_rn(t1, t3);
                    M[i] = __fmul_rn(U[i][j], Vij);
                }
                s0[j] = __fadd_rn(__fadd_rn(M[0], M[1]), M[2]);
                s1[j] = __fsub_rn(__fsub_rn(M[1], M[2]), M[3]);
            }
            float y[4];
            y[0] = __fadd_rn(__fadd_rn(s0[0], s0[1]), s0[2]);   // (0,0)
            y[1] = __fsub_rn(__fsub_rn(s0[1], s0[2]), s0[3]);   // (0,1)
            y[2] = __fadd_rn(__fadd_rn(s1[0], s1[1]), s1[2]);   // (1,0)
            y[3] = __fsub_rn(__fsub_rn(s1[1], s1[2]), s1[3]);   // (1,1)

            // ---- refractory: IIR fast path + warp-voted exact fallback ----
            float rnew[4];
            bool  sp[4];
            bool  band = false;
#pragma unroll
            for (int p = 0; p < 4; ++p) {
                float rt = fmaf(A1, r1[p], fmaf(A2, r2[p], __fmul_rn(RK1, sf[p])));
                rnew[p]  = rt;
                float d  = __fsub_rn(__fadd_rn(y[p], rt), THETA);
                sp[p]    = (d > 0.0f);
                band    |= (fabsf(d) <= EPS);
            }
            if (__ballot_sync(0xffffffffu, band)) {
                // uniform warp branch: exact descending-j sums (reference order)
#pragma unroll
                for (int p = 0; p < 4; ++p) {
                    float r = 0.0f;
#pragma unroll
                    for (int j = JMAX; j >= 1; --j)       // s_rk[j]: broadcast LDS
                        if ((win[p] >> (j - 1)) & 1ull) r = __fadd_rn(r, s_rk[j]);
                    sp[p] = (__fadd_rn(y[p], r) >= THETA);
                }
            }
#pragma unroll
            for (int p = 0; p < 4; ++p) {
                unsigned long long spb = sp[p] ? 1ull : 0ull;
                sm[p]  |= spb << t;
                win[p]  = (win[p] << 1) | spb;
                r2[p] = r1[p];
                r1[p] = rnew[p];
                sf[p] = sp[p] ? 1.0f : 0.0f;
            }
        }
        __syncthreads();
    }

    // ---- epilogue ----
#pragma unroll
    for (int p = 0; p < 4; ++p) {
        const int h   = h0 + 2 * tr + (p >> 1);
        const int wc  = 2 * tcix + (p & 1);
        const int loc = (b * H_ + h) * W_ + wc;
        if (LAYER == 0) {
            g_s1bits[loc] = sm[p];
        } else {
            float4* o = (float4*)(out + (size_t)loc * T_);
            const unsigned long long sv = sm[p];
#pragma unroll
            for (int i = 0; i < 16; ++i) {
                float4 v;
                v.x = ((sv >> (4 * i + 0)) & 1ull) ? 1.0f : 0.0f;
                v.y = ((sv >> (4 * i + 1)) & 1ull) ? 1.0f : 0.0f;
                v.z = ((sv >> (4 * i + 2)) & 1ull) ? 1.0f : 0.0f;
                v.w = ((sv >> (4 * i + 3)) & 1ull) ? 1.0f : 0.0f;
                o[i] = v;
            }
        }
    }
}

// ---------------------------------------------------------------------------
extern "C" void kernel_launch(void* const* d_in, const int* in_sizes, int n_in,
                              void* d_out, int out_size) {
    const float* x  = (const float*)d_in[0];
    const float* w1 = (const float*)d_in[1];
    const float* w2 = (const float*)d_in[2];
    float* out = (float*)d_out;

    dim3 pblk(64, 4), pgrd(H_ / 4, B_);
    pack_kernel<<<pgrd, pblk>>>(x);

    dim3 fblk(128), fgrd(H_ / 8, B_);
    fused_kernel<0><<<fgrd, fblk>>>(w1, nullptr);
    fused_kernel<1><<<fgrd, fblk>>>(w2, out);
}